// round 16
// baseline (speedup 1.0000x reference)
#include <cuda_runtime.h>
#include <cuda_fp16.h>
#include <math_constants.h>
#include <cstdint>

// Problem constants:
//   x: [N, D] fp32,  cb: [K, D] fp32 (unit rows)
//   sims = x @ cb^T [N,K]; labels = argmax_k (first occurrence); preds = cb[labels]
#define NN 131072
#define DD 512
#define KK 2048

#define BM 128
#define BN 128
#define BK 64
#define NITERS (DD / BK)    // 8
#define STAGES 3
#define STAGE_BYTES 32768   // A: 128x64 half (16KB) + B: 128x64 half (16KB)
#define SMEM_BYTES (STAGES * STAGE_BYTES)   // 98304 (x2 blocks/SM = 192KB < 228KB)

#define MARGIN 8e-3f
#define MAXCAND 8
#define NBX (KK / BN)       // 16 column-blocks per row
#define NBY (NN / BM)       // 1024 row-groups

// Pre-converted fp16 inputs (row-major, contiguous)
__device__ __align__(16) half g_xh[(size_t)NN * DD];
__device__ __align__(16) half g_cbh[(size_t)KK * DD];

// Per-(row, col-block) argmax partials: top-1 value/index + top-2 value
__device__ float g_p1v[(size_t)NN * NBX];
__device__ int   g_p1i[(size_t)NN * NBX];
__device__ float g_p2v[(size_t)NN * NBX];

// last-block tickets per row-group + near-tie worklist
__device__ int g_tick[NBY];
__device__ int g_cnt;
__device__ int g_work[NN];

__device__ __forceinline__ uint32_t h2u(half2 h) {
    return *reinterpret_cast<uint32_t*>(&h);
}
__device__ __forceinline__ uint32_t smem_u32(const void* p) {
    uint32_t a;
    asm("{ .reg .u64 t; cvta.to.shared.u64 t, %1; cvt.u32.u64 %0, t; }" : "=r"(a) : "l"(p));
    return a;
}
#define SW128(b) ((b) ^ (((b) >> 3) & 0x70))

__device__ __forceinline__ void cp_async16(uint32_t saddr, const void* gaddr) {
    asm volatile("cp.async.cg.shared.global [%0], [%1], 16;"
                 :: "r"(saddr), "l"(gaddr) : "memory");
}
#define CP_COMMIT()  asm volatile("cp.async.commit_group;" ::: "memory")
#define CP_WAIT(N)   asm volatile("cp.async.wait_group %0;" :: "n"(N) : "memory")

__device__ __forceinline__ void ldsm_x4(uint32_t* r, uint32_t addr) {
    asm volatile("ldmatrix.sync.aligned.m8n8.x4.shared.b16 {%0,%1,%2,%3}, [%4];"
                 : "=r"(r[0]), "=r"(r[1]), "=r"(r[2]), "=r"(r[3]) : "r"(addr));
}
__device__ __forceinline__ void ldsm_x2(uint32_t* r, uint32_t addr) {
    asm volatile("ldmatrix.sync.aligned.m8n8.x2.shared.b16 {%0,%1}, [%2];"
                 : "=r"(r[0]), "=r"(r[1]) : "r"(addr));
}
__device__ __forceinline__ void mma16816(float* d, const uint32_t* a, const uint32_t* b) {
    asm volatile(
        "mma.sync.aligned.m16n8k16.row.col.f32.f16.f16.f32 "
        "{%0,%1,%2,%3}, {%4,%5,%6,%7}, {%8,%9}, {%0,%1,%2,%3};"
        : "+f"(d[0]), "+f"(d[1]), "+f"(d[2]), "+f"(d[3])
        : "r"(a[0]), "r"(a[1]), "r"(a[2]), "r"(a[3]), "r"(b[0]), "r"(b[1]));
}

// top-2 helpers -------------------------------------------------------------
__device__ __forceinline__ void top2_push(float& v1, int& i1, float& v2,
                                          float v, int idx) {
    if (v > v1 || (v == v1 && idx < i1)) { v2 = v1; v1 = v; i1 = idx; }
    else                                 { v2 = fmaxf(v2, v); }
}
__device__ __forceinline__ void top2_merge(float& v1, int& i1, float& v2,
                                           float b1, int bi, float b2) {
    if (b1 > v1 || (b1 == v1 && bi < i1)) { v2 = fmaxf(v1, b2); v1 = b1; i1 = bi; }
    else                                  { v2 = fmaxf(v2, b1); }
}

// ---------------------------------------------------------------------------
// Pre-pass: fp32 -> fp16 conversion; block 0 also zeroes tickets + worklist.
// ---------------------------------------------------------------------------
__global__ __launch_bounds__(256)
void cvt_f16_kernel(const float4* __restrict__ src, uint2* __restrict__ dst,
                    int clear_state) {
    if (clear_state && blockIdx.x == 0) {
        if (threadIdx.x == 0) g_cnt = 0;
#pragma unroll
        for (int k = 0; k < NBY / 256; ++k) g_tick[threadIdx.x + k * 256] = 0;
    }
    size_t i = (size_t)blockIdx.x * blockDim.x + threadIdx.x;
    float4 v = src[i];
    half2 h01 = __float22half2_rn(make_float2(v.x, v.y));
    half2 h23 = __float22half2_rn(make_float2(v.z, v.w));
    dst[i] = make_uint2(h2u(h01), h2u(h23));
}

// ---------------------------------------------------------------------------
// Kernel 1: fp16 GEMM (cp.async 3-stage, single sync/iter) with fused top-2
// epilogue AND last-block-per-row-group reduction (labels + preds gather).
// ---------------------------------------------------------------------------
__global__ __launch_bounds__(256, 2)
void gemm_f16_kernel(float* __restrict__ C,
                     const float* __restrict__ cb,
                     float* __restrict__ preds,
                     void* __restrict__ labels,
                     int labels_are_i64)
{
    extern __shared__ char smem[];
    const uint32_t sbase = smem_u32(smem);
    const int tid = threadIdx.x;
    const int lane = tid & 31;
    const int wid = tid >> 5;
    const int wm = wid & 1;          // 2 m-warps (64 rows each)
    const int wn = wid >> 1;         // 4 n-warps (32 cols each)
    const int bm = blockIdx.y * BM;
    const int bn = blockIdx.x * BN;

    const int prow = tid >> 3;       // cp.async producer: base row
    const int pc   = tid & 7;        // 16B chunk within 128B row

    auto issue_stage = [&](int it) {
        const int st = it % STAGES;
        const uint32_t abase = sbase + st * STAGE_BYTES;
        const uint32_t bbase = abase + 16384;
        const int kk = it * BK;
#pragma unroll
        for (int j = 0; j < 4; ++j) {
            const int row = prow + j * 32;
            const uint32_t sw = SW128((uint32_t)(row * 128 + pc * 16));
            cp_async16(abase + sw, g_xh  + (size_t)(bm + row) * DD + kk + pc * 8);
            cp_async16(bbase + sw, g_cbh + (size_t)(bn + row) * DD + kk + pc * 8);
        }
        CP_COMMIT();
    };

    float acc[4][4][4];
#pragma unroll
    for (int i = 0; i < 4; ++i)
#pragma unroll
        for (int j = 0; j < 4; ++j)
#pragma unroll
            for (int r = 0; r < 4; ++r) acc[i][j][r] = 0.0f;

    issue_stage(0);
    issue_stage(1);

#pragma unroll 1
    for (int it = 0; it < NITERS; ++it) {
        CP_WAIT(1);                  // stage it landed (<=1 group pending)
        __syncthreads();             // + all warps done with stage it-1

        const uint32_t abase = sbase + (it % STAGES) * STAGE_BYTES;
        const uint32_t bbase = abase + 16384;

#pragma unroll
        for (int s = 0; s < 4; ++s) {
            uint32_t ah[4][4], bh[4][2];
#pragma unroll
            for (int i = 0; i < 4; ++i) {
                const int r = wm * 64 + i * 16 + (lane & 15);
                const uint32_t off = (uint32_t)(r * 128 + s * 32 + ((lane >> 4) << 4));
                ldsm_x4(ah[i], abase + SW128(off));
            }
#pragma unroll
            for (int j = 0; j < 4; ++j) {
                const int r = wn * 32 + j * 8 + (lane & 7);
                const uint32_t off = (uint32_t)(r * 128 + s * 32 + (((lane >> 3) & 1) << 4));
                ldsm_x2(bh[j], bbase + SW128(off));
            }
#pragma unroll
            for (int i = 0; i < 4; ++i)
#pragma unroll
                for (int j = 0; j < 4; ++j) mma16816(acc[i][j], ah[i], bh[j]);
        }

        // safe without a second barrier: writes buffer (it+2)%3 == (it-1)%3,
        // which the top-of-iter barrier proved fully consumed.
        if (it + 2 < NITERS) issue_stage(it + 2);
    }

    // ---- epilogue 1: write sims ----
#pragma unroll
    for (int i = 0; i < 4; ++i) {
        int r0 = bm + wm * 64 + i * 16 + (lane >> 2);
#pragma unroll
        for (int j = 0; j < 4; ++j) {
            int c = bn + wn * 32 + j * 8 + (lane & 3) * 2;
            *(float2*)&C[(size_t)r0 * KK + c] = make_float2(acc[i][j][0], acc[i][j][1]);
            *(float2*)&C[(size_t)(r0 + 8) * KK + c] = make_float2(acc[i][j][2], acc[i][j][3]);
        }
    }

    // ---- epilogue 2: per-row top-2 over this block's 128 cols ----
    float* s_v1 = (float*)smem;              // 4*128 floats
    int*   s_i1 = (int*)(smem + 2048);
    float* s_v2 = (float*)(smem + 4096);
    __syncthreads();                          // pipeline drained; reuse smem

#pragma unroll
    for (int i = 0; i < 4; ++i) {
        float v1a = -CUDART_INF_F, v2a = -CUDART_INF_F;
        float v1b = -CUDART_INF_F, v2b = -CUDART_INF_F;
        int i1a = 0x7FFFFFFF, i1b = 0x7FFFFFFF;
#pragma unroll
        for (int j = 0; j < 4; ++j) {
            int c = bn + wn * 32 + j * 8 + (lane & 3) * 2;
            top2_push(v1a, i1a, v2a, acc[i][j][0], c);
            top2_push(v1a, i1a, v2a, acc[i][j][1], c + 1);
            top2_push(v1b, i1b, v2b, acc[i][j][2], c);
            top2_push(v1b, i1b, v2b, acc[i][j][3], c + 1);
        }
#pragma unroll
        for (int m = 1; m <= 2; m <<= 1) {
            float b1 = __shfl_xor_sync(0xFFFFFFFFu, v1a, m);
            int   bi = __shfl_xor_sync(0xFFFFFFFFu, i1a, m);
            float b2 = __shfl_xor_sync(0xFFFFFFFFu, v2a, m);
            top2_merge(v1a, i1a, v2a, b1, bi, b2);
            b1 = __shfl_xor_sync(0xFFFFFFFFu, v1b, m);
            bi = __shfl_xor_sync(0xFFFFFFFFu, i1b, m);
            b2 = __shfl_xor_sync(0xFFFFFFFFu, v2b, m);
            top2_merge(v1b, i1b, v2b, b1, bi, b2);
        }
        if ((lane & 3) == 0) {
            int rA = wm * 64 + i * 16 + (lane >> 2);
            s_v1[wn * 128 + rA] = v1a; s_i1[wn * 128 + rA] = i1a; s_v2[wn * 128 + rA] = v2a;
            s_v1[wn * 128 + rA + 8] = v1b; s_i1[wn * 128 + rA + 8] = i1b; s_v2[wn * 128 + rA + 8] = v2b;
        }
    }
    __syncthreads();

    if (tid < 128) {
        float V1 = s_v1[tid]; int I1 = s_i1[tid]; float V2 = s_v2[tid];
#pragma unroll
        for (int w = 1; w < 4; ++w)
            top2_merge(V1, I1, V2, s_v1[w * 128 + tid], s_i1[w * 128 + tid], s_v2[w * 128 + tid]);
        size_t p = (size_t)(bm + tid) * NBX + blockIdx.x;
        g_p1v[p] = V1; g_p1i[p] = I1; g_p2v[p] = V2;
    }

    // ---- epilogue 3: last block of this row-group reduces + emits outputs ----
    __shared__ int s_winner;
    __syncthreads();
    if (tid == 0) {
        __threadfence();   // make partials visible before the ticket
        s_winner = (atomicAdd(&g_tick[blockIdx.y], 1) == NBX - 1);
    }
    __syncthreads();
    if (!s_winner) return;
    __threadfence();       // see all other blocks' partials

    const int warp = wid;  // 8 warps, warp per row, 16 rounds
#pragma unroll 1
    for (int rr = warp; rr < BM; rr += 8) {
        const int n = bm + rr;
        float V1 = -CUDART_INF_F, V2 = -CUDART_INF_F;
        int I1 = 0x7FFFFFFF;
        if (lane < NBX) {
            size_t p = (size_t)n * NBX + lane;
            V1 = g_p1v[p]; I1 = g_p1i[p]; V2 = g_p2v[p];
        }
#pragma unroll
        for (int off = 16; off > 0; off >>= 1) {
            float b1 = __shfl_xor_sync(0xFFFFFFFFu, V1, off);
            int   bi = __shfl_xor_sync(0xFFFFFFFFu, I1, off);
            float b2 = __shfl_xor_sync(0xFFFFFFFFu, V2, off);
            top2_merge(V1, I1, V2, b1, bi, b2);
        }
        if (V1 - V2 > MARGIN) {
            if (lane == 0) {
                if (labels_are_i64) ((long long*)labels)[n] = (long long)I1;
                else                ((float*)labels)[n] = (float)I1;
            }
            const float4* src = (const float4*)(cb + (size_t)I1 * DD);
            float4* dst = (float4*)(preds + (size_t)n * DD);
#pragma unroll
            for (int k = 0; k < 4; ++k) dst[lane + k * 32] = src[lane + k * 32];
        } else if (lane == 0) {
            int w = atomicAdd(&g_cnt, 1);
            g_work[w] = n;
        }
    }
}

// ---------------------------------------------------------------------------
// Kernel 2: worklist fixup — full-row candidate collection + bitwise-faithful
// sequential-fp32 fmaf re-score, then label + gather for near-tie rows.
// ---------------------------------------------------------------------------
__global__ __launch_bounds__(256)
void fixup_kernel(const float* __restrict__ sims,
                  const float* __restrict__ cb,
                  const float* __restrict__ x,
                  float* __restrict__ preds,
                  void* __restrict__ labels,
                  int labels_are_i64)
{
    const int tid = threadIdx.x;
    const int lane = tid & 31, warp = tid >> 5;

    __shared__ float swm[8];
    __shared__ int   swi[8];
    __shared__ int   s_final;
    __shared__ float s_exact[MAXCAND];
    __shared__ float sx[DD];
    __shared__ float scs[MAXCAND][DD];

    const int total = g_cnt;
#pragma unroll 1
    for (int w = blockIdx.x; w < total; w += gridDim.x) {
        const int n = g_work[w];
        const float4* row = (const float4*)(sims + (size_t)n * KK);

        float4 va = row[tid];
        float4 vb = row[tid + 256];
        float v[8] = {va.x, va.y, va.z, va.w, vb.x, vb.y, vb.z, vb.w};

        float m = fmaxf(fmaxf(fmaxf(v[0], v[1]), fmaxf(v[2], v[3])),
                        fmaxf(fmaxf(v[4], v[5]), fmaxf(v[6], v[7])));
#pragma unroll
        for (int off = 16; off > 0; off >>= 1)
            m = fmaxf(m, __shfl_xor_sync(0xFFFFFFFFu, m, off));
        if (lane == 0) swm[warp] = m;
        __syncthreads();
        float bv = swm[0];
#pragma unroll
        for (int ww = 1; ww < 8; ++ww) bv = fmaxf(bv, swm[ww]);
        const float thr = bv - MARGIN;

        int cand[MAXCAND];
        int ccount = 0;
        int last = -1;
#pragma unroll 1
        for (int c = 0; c < MAXCAND; ++c) {
            int my = 0x7FFFFFFF;
#pragma unroll
            for (int e = 0; e < 8; ++e) {
                int g = (e < 4) ? tid * 4 + e : (tid + 256) * 4 + (e - 4);
                if (v[e] > thr && g > last) my = min(my, g);
            }
#pragma unroll
            for (int off = 16; off > 0; off >>= 1)
                my = min(my, __shfl_xor_sync(0xFFFFFFFFu, my, off));
            __syncthreads();
            if (lane == 0) swi[warp] = my;
            __syncthreads();
            int fnd = swi[0];
#pragma unroll
            for (int ww = 1; ww < 8; ++ww) fnd = min(fnd, swi[ww]);
            if (fnd == 0x7FFFFFFF) break;
            cand[ccount++] = fnd;
            last = fnd;
        }

        for (int d = tid; d < DD; d += 256) {
            sx[d] = x[(size_t)n * DD + d];
            for (int c = 0; c < ccount; ++c)
                scs[c][d] = cb[(size_t)cand[c] * DD + d];
        }
        __syncthreads();

        if (tid < ccount) {
            const float* cr = scs[tid];
            float s = 0.0f;
#pragma unroll 8
            for (int d = 0; d < DD; ++d) s = fmaf(sx[d], cr[d], s);
            s_exact[tid] = s;
        }
        __syncthreads();
        if (tid == 0) {
            float bvv = s_exact[0];
            int bii = cand[0];
            for (int c = 1; c < ccount; ++c)
                if (s_exact[c] > bvv) { bvv = s_exact[c]; bii = cand[c]; }
            s_final = bii;
        }
        __syncthreads();

        const int lbl = s_final;
        if (tid == 0) {
            if (labels_are_i64) ((long long*)labels)[n] = (long long)lbl;
            else                ((float*)labels)[n] = (float)lbl;
        }
        if (tid < 128) {
            float4 c = ((const float4*)(cb + (size_t)lbl * DD))[tid];
            ((float4*)(preds + (size_t)n * DD))[tid] = c;
        }
        __syncthreads();
    }
}

// ---------------------------------------------------------------------------
// Launch
// ---------------------------------------------------------------------------
extern "C" void kernel_launch(void* const* d_in, const int* in_sizes, int n_in,
                              void* d_out, int out_size)
{
    const float* x  = (const float*)d_in[0];   // [N, D]
    const float* cb = (const float*)d_in[1];   // [K, D]

    float* out = (float*)d_out;
    const size_t predsSz = (size_t)NN * DD;
    const size_t simsSz  = (size_t)NN * KK;

    size_t labelElems;
    int labels_are_i64;
    if ((size_t)(unsigned)out_size == predsSz + 2 * (size_t)NN + simsSz) {
        labelElems = 2 * (size_t)NN; labels_are_i64 = 1;
    } else {
        labelElems = (size_t)NN;     labels_are_i64 = 0;
    }

    float* preds  = out;
    void*  labels = (void*)(out + predsSz);
    float* sims   = out + predsSz + labelElems;

    static int attr_set = 0;
    if (!attr_set) {
        cudaFuncSetAttribute(gemm_f16_kernel,
                             cudaFuncAttributeMaxDynamicSharedMemorySize, SMEM_BYTES);
        attr_set = 1;
    }

    // fp16 pre-conversion (also resets tickets + worklist counter)
    half* xh_p;  cudaGetSymbolAddress((void**)&xh_p,  g_xh);
    half* cbh_p; cudaGetSymbolAddress((void**)&cbh_p, g_cbh);
    cvt_f16_kernel<<<(NN * DD / 4) / 256, 256>>>((const float4*)x,  (uint2*)xh_p, 1);
    cvt_f16_kernel<<<(KK * DD / 4) / 256, 256>>>((const float4*)cb, (uint2*)cbh_p, 0);

    dim3 grid(KK / BN, NN / BM);   // (16, 1024)
    gemm_f16_kernel<<<grid, 256, SMEM_BYTES>>>(sims, cb, preds, labels, labels_are_i64);
    fixup_kernel<<<2048, 256>>>(sims, cb, x, preds, labels, labels_are_i64);
}

// round 17
// speedup vs baseline: 1.2256x; 1.2256x over previous
#include <cuda_runtime.h>
#include <cuda_fp16.h>
#include <math_constants.h>
#include <cstdint>

// Problem constants:
//   x: [N, D] fp32,  cb: [K, D] fp32 (unit rows)
//   sims = x @ cb^T [N,K]; labels = argmax_k (first occurrence); preds = cb[labels]
#define NN 131072
#define DD 512
#define KK 2048

#define BM 128
#define BN 128
#define BK 64
#define NITERS (DD / BK)    // 8
#define STAGES 3
#define STAGE_BYTES 32768   // A: 128x64 half (16KB) + B: 128x64 half (16KB)
#define SMEM_BYTES (STAGES * STAGE_BYTES)   // 98304 (x2 blocks/SM = 192KB < 228KB)

#define MARGIN 8e-3f
#define MAXCAND 8
#define NBX (KK / BN)       // 16 column-blocks per row

// Pre-converted fp16 inputs (row-major, contiguous)
__device__ __align__(16) half g_xh[(size_t)NN * DD];
__device__ __align__(16) half g_cbh[(size_t)KK * DD];

// Per-(row, col-block) argmax partials: top-1 value/index + top-2 value
__device__ float g_p1v[(size_t)NN * NBX];
__device__ int   g_p1i[(size_t)NN * NBX];
__device__ float g_p2v[(size_t)NN * NBX];

// Near-tie worklist
__device__ int g_cnt;
__device__ int g_work[NN];

__device__ __forceinline__ uint32_t h2u(half2 h) {
    return *reinterpret_cast<uint32_t*>(&h);
}
__device__ __forceinline__ uint32_t smem_u32(const void* p) {
    uint32_t a;
    asm("{ .reg .u64 t; cvta.to.shared.u64 t, %1; cvt.u32.u64 %0, t; }" : "=r"(a) : "l"(p));
    return a;
}
#define SW128(b) ((b) ^ (((b) >> 3) & 0x70))

__device__ __forceinline__ void cp_async16(uint32_t saddr, const void* gaddr) {
    asm volatile("cp.async.cg.shared.global [%0], [%1], 16;"
                 :: "r"(saddr), "l"(gaddr) : "memory");
}
#define CP_COMMIT()  asm volatile("cp.async.commit_group;" ::: "memory")
#define CP_WAIT(N)   asm volatile("cp.async.wait_group %0;" :: "n"(N) : "memory")

__device__ __forceinline__ void ldsm_x4(uint32_t* r, uint32_t addr) {
    asm volatile("ldmatrix.sync.aligned.m8n8.x4.shared.b16 {%0,%1,%2,%3}, [%4];"
                 : "=r"(r[0]), "=r"(r[1]), "=r"(r[2]), "=r"(r[3]) : "r"(addr));
}
__device__ __forceinline__ void ldsm_x2(uint32_t* r, uint32_t addr) {
    asm volatile("ldmatrix.sync.aligned.m8n8.x2.shared.b16 {%0,%1}, [%2];"
                 : "=r"(r[0]), "=r"(r[1]) : "r"(addr));
}
__device__ __forceinline__ void mma16816(float* d, const uint32_t* a, const uint32_t* b) {
    asm volatile(
        "mma.sync.aligned.m16n8k16.row.col.f32.f16.f16.f32 "
        "{%0,%1,%2,%3}, {%4,%5,%6,%7}, {%8,%9}, {%0,%1,%2,%3};"
        : "+f"(d[0]), "+f"(d[1]), "+f"(d[2]), "+f"(d[3])
        : "r"(a[0]), "r"(a[1]), "r"(a[2]), "r"(a[3]), "r"(b[0]), "r"(b[1]));
}

// top-2 helpers -------------------------------------------------------------
__device__ __forceinline__ void top2_push(float& v1, int& i1, float& v2,
                                          float v, int idx) {
    if (v > v1 || (v == v1 && idx < i1)) { v2 = v1; v1 = v; i1 = idx; }
    else                                 { v2 = fmaxf(v2, v); }
}
__device__ __forceinline__ void top2_merge(float& v1, int& i1, float& v2,
                                           float b1, int bi, float b2) {
    if (b1 > v1 || (b1 == v1 && bi < i1)) { v2 = fmaxf(v1, b2); v1 = b1; i1 = bi; }
    else                                  { v2 = fmaxf(v2, b1); }
}

// ---------------------------------------------------------------------------
// Pre-pass: fp32 -> fp16 row-major conversion (also zeroes the worklist count)
// ---------------------------------------------------------------------------
__global__ __launch_bounds__(256)
void cvt_f16_kernel(const float4* __restrict__ src, uint2* __restrict__ dst) {
    if (blockIdx.x == 0 && threadIdx.x == 0) g_cnt = 0;
    size_t i = (size_t)blockIdx.x * blockDim.x + threadIdx.x;
    float4 v = src[i];
    half2 h01 = __float22half2_rn(make_float2(v.x, v.y));
    half2 h23 = __float22half2_rn(make_float2(v.z, v.w));
    dst[i] = make_uint2(h2u(h01), h2u(h23));
}

// ---------------------------------------------------------------------------
// Kernel 1: fp16 GEMM (cp.async 3-stage + ldmatrix), occ=2, ONE barrier per
// k-iteration. Correct tail: the group being consumed is always drained
// (CP_WAIT(0) on the final iteration — this was the R15 race).
// Bottom-issue writes buffer (it-1)%3, proven consumed by the top-of-iter
// barrier. Fused per-block top-2 argmax partials in the epilogue.
// ---------------------------------------------------------------------------
__global__ __launch_bounds__(256, 2)
void gemm_f16_kernel(float* __restrict__ C)
{
    extern __shared__ char smem[];
    const uint32_t sbase = smem_u32(smem);
    const int tid = threadIdx.x;
    const int lane = tid & 31;
    const int wid = tid >> 5;
    const int wm = wid & 1;          // 2 m-warps (64 rows each)
    const int wn = wid >> 1;         // 4 n-warps (32 cols each)
    const int bm = blockIdx.y * BM;
    const int bn = blockIdx.x * BN;

    const int prow = tid >> 3;       // cp.async producer: base row
    const int pc   = tid & 7;        // 16B chunk within 128B row

    auto issue_stage = [&](int it) {
        const int st = it % STAGES;
        const uint32_t abase = sbase + st * STAGE_BYTES;
        const uint32_t bbase = abase + 16384;
        const int kk = it * BK;
#pragma unroll
        for (int j = 0; j < 4; ++j) {
            const int row = prow + j * 32;
            const uint32_t sw = SW128((uint32_t)(row * 128 + pc * 16));
            cp_async16(abase + sw, g_xh  + (size_t)(bm + row) * DD + kk + pc * 8);
            cp_async16(bbase + sw, g_cbh + (size_t)(bn + row) * DD + kk + pc * 8);
        }
        CP_COMMIT();
    };

    float acc[4][4][4];
#pragma unroll
    for (int i = 0; i < 4; ++i)
#pragma unroll
        for (int j = 0; j < 4; ++j)
#pragma unroll
            for (int r = 0; r < 4; ++r) acc[i][j][r] = 0.0f;

    issue_stage(0);
    issue_stage(1);

#pragma unroll 1
    for (int it = 0; it < NITERS; ++it) {
        if (it + 1 < NITERS) { CP_WAIT(1); }   // newest group may stay pending
        else                 { CP_WAIT(0); }   // tail: drain the group we consume
        __syncthreads();     // all warps done with stage it-1 + stage it visible

        const uint32_t abase = sbase + (it % STAGES) * STAGE_BYTES;
        const uint32_t bbase = abase + 16384;

#pragma unroll
        for (int s = 0; s < 4; ++s) {
            uint32_t ah[4][4], bh[4][2];
#pragma unroll
            for (int i = 0; i < 4; ++i) {
                const int r = wm * 64 + i * 16 + (lane & 15);
                const uint32_t off = (uint32_t)(r * 128 + s * 32 + ((lane >> 4) << 4));
                ldsm_x4(ah[i], abase + SW128(off));
            }
#pragma unroll
            for (int j = 0; j < 4; ++j) {
                const int r = wn * 32 + j * 8 + (lane & 7);
                const uint32_t off = (uint32_t)(r * 128 + s * 32 + (((lane >> 3) & 1) << 4));
                ldsm_x2(bh[j], bbase + SW128(off));
            }
#pragma unroll
            for (int i = 0; i < 4; ++i)
#pragma unroll
                for (int j = 0; j < 4; ++j) mma16816(acc[i][j], ah[i], bh[j]);
        }

        // writes buffer (it+2)%3 == (it-1)%3, consumed before this iter's barrier
        if (it + 2 < NITERS) issue_stage(it + 2);
    }

    // ---- epilogue 1: write sims ----
#pragma unroll
    for (int i = 0; i < 4; ++i) {
        int r0 = bm + wm * 64 + i * 16 + (lane >> 2);
#pragma unroll
        for (int j = 0; j < 4; ++j) {
            int c = bn + wn * 32 + j * 8 + (lane & 3) * 2;
            *(float2*)&C[(size_t)r0 * KK + c] = make_float2(acc[i][j][0], acc[i][j][1]);
            *(float2*)&C[(size_t)(r0 + 8) * KK + c] = make_float2(acc[i][j][2], acc[i][j][3]);
        }
    }

    // ---- epilogue 2: per-row top-2 over this block's 128 cols ----
    float* s_v1 = (float*)smem;              // reuses stage-0 bytes (drained)
    int*   s_i1 = (int*)(smem + 2048);
    float* s_v2 = (float*)(smem + 4096);
    __syncthreads();                          // defensive: all consume done

#pragma unroll
    for (int i = 0; i < 4; ++i) {
        float v1a = -CUDART_INF_F, v2a = -CUDART_INF_F;
        float v1b = -CUDART_INF_F, v2b = -CUDART_INF_F;
        int i1a = 0x7FFFFFFF, i1b = 0x7FFFFFFF;
#pragma unroll
        for (int j = 0; j < 4; ++j) {
            int c = bn + wn * 32 + j * 8 + (lane & 3) * 2;
            top2_push(v1a, i1a, v2a, acc[i][j][0], c);
            top2_push(v1a, i1a, v2a, acc[i][j][1], c + 1);
            top2_push(v1b, i1b, v2b, acc[i][j][2], c);
            top2_push(v1b, i1b, v2b, acc[i][j][3], c + 1);
        }
#pragma unroll
        for (int m = 1; m <= 2; m <<= 1) {
            float b1 = __shfl_xor_sync(0xFFFFFFFFu, v1a, m);
            int   bi = __shfl_xor_sync(0xFFFFFFFFu, i1a, m);
            float b2 = __shfl_xor_sync(0xFFFFFFFFu, v2a, m);
            top2_merge(v1a, i1a, v2a, b1, bi, b2);
            b1 = __shfl_xor_sync(0xFFFFFFFFu, v1b, m);
            bi = __shfl_xor_sync(0xFFFFFFFFu, i1b, m);
            b2 = __shfl_xor_sync(0xFFFFFFFFu, v2b, m);
            top2_merge(v1b, i1b, v2b, b1, bi, b2);
        }
        if ((lane & 3) == 0) {
            int rA = wm * 64 + i * 16 + (lane >> 2);
            s_v1[wn * 128 + rA] = v1a; s_i1[wn * 128 + rA] = i1a; s_v2[wn * 128 + rA] = v2a;
            s_v1[wn * 128 + rA + 8] = v1b; s_i1[wn * 128 + rA + 8] = i1b; s_v2[wn * 128 + rA + 8] = v2b;
        }
    }
    __syncthreads();

    if (tid < 128) {
        float V1 = s_v1[tid]; int I1 = s_i1[tid]; float V2 = s_v2[tid];
#pragma unroll
        for (int w = 1; w < 4; ++w)
            top2_merge(V1, I1, V2, s_v1[w * 128 + tid], s_i1[w * 128 + tid], s_v2[w * 128 + tid]);
        size_t p = (size_t)(bm + tid) * NBX + blockIdx.x;
        g_p1v[p] = V1; g_p1i[p] = I1; g_p2v[p] = V2;
    }
}

// ---------------------------------------------------------------------------
// Kernel 2: reduce partials -> label + gather (fast path), or enqueue row.
// One warp per row.
// ---------------------------------------------------------------------------
__global__ __launch_bounds__(256)
void reduce_label_kernel(const float* __restrict__ cb,
                         float* __restrict__ preds,
                         void* __restrict__ labels,
                         int labels_are_i64)
{
    const int n = blockIdx.x * 8 + (threadIdx.x >> 5);
    const int lane = threadIdx.x & 31;

    float V1 = -CUDART_INF_F, V2 = -CUDART_INF_F;
    int I1 = 0x7FFFFFFF;
    if (lane < NBX) {
        size_t p = (size_t)n * NBX + lane;
        V1 = g_p1v[p]; I1 = g_p1i[p]; V2 = g_p2v[p];
    }
#pragma unroll
    for (int off = 16; off > 0; off >>= 1) {
        float b1 = __shfl_xor_sync(0xFFFFFFFFu, V1, off);
        int   bi = __shfl_xor_sync(0xFFFFFFFFu, I1, off);
        float b2 = __shfl_xor_sync(0xFFFFFFFFu, V2, off);
        top2_merge(V1, I1, V2, b1, bi, b2);
    }

    if (V1 - V2 > MARGIN) {
        if (lane == 0) {
            if (labels_are_i64) ((long long*)labels)[n] = (long long)I1;
            else                ((float*)labels)[n] = (float)I1;
        }
        const float4* src = (const float4*)(cb + (size_t)I1 * DD);
        float4* dst = (float4*)(preds + (size_t)n * DD);
#pragma unroll
        for (int k = 0; k < 4; ++k) dst[lane + k * 32] = src[lane + k * 32];
    } else if (lane == 0) {
        int w = atomicAdd(&g_cnt, 1);
        g_work[w] = n;
    }
}

// ---------------------------------------------------------------------------
// Kernel 3: worklist fixup — full-row candidate collection + bitwise-faithful
// sequential-fp32 fmaf re-score, then label + gather for near-tie rows.
// ---------------------------------------------------------------------------
__global__ __launch_bounds__(256)
void fixup_kernel(const float* __restrict__ sims,
                  const float* __restrict__ cb,
                  const float* __restrict__ x,
                  float* __restrict__ preds,
                  void* __restrict__ labels,
                  int labels_are_i64)
{
    const int tid = threadIdx.x;
    const int lane = tid & 31, warp = tid >> 5;

    __shared__ float swm[8];
    __shared__ int   swi[8];
    __shared__ int   s_final;
    __shared__ float s_exact[MAXCAND];
    __shared__ float sx[DD];
    __shared__ float scs[MAXCAND][DD];

    const int total = g_cnt;
#pragma unroll 1
    for (int w = blockIdx.x; w < total; w += gridDim.x) {
        const int n = g_work[w];
        const float4* row = (const float4*)(sims + (size_t)n * KK);

        float4 va = row[tid];
        float4 vb = row[tid + 256];
        float v[8] = {va.x, va.y, va.z, va.w, vb.x, vb.y, vb.z, vb.w};

        float m = fmaxf(fmaxf(fmaxf(v[0], v[1]), fmaxf(v[2], v[3])),
                        fmaxf(fmaxf(v[4], v[5]), fmaxf(v[6], v[7])));
#pragma unroll
        for (int off = 16; off > 0; off >>= 1)
            m = fmaxf(m, __shfl_xor_sync(0xFFFFFFFFu, m, off));
        if (lane == 0) swm[warp] = m;
        __syncthreads();
        float bv = swm[0];
#pragma unroll
        for (int ww = 1; ww < 8; ++ww) bv = fmaxf(bv, swm[ww]);
        const float thr = bv - MARGIN;

        int cand[MAXCAND];
        int ccount = 0;
        int last = -1;
#pragma unroll 1
        for (int c = 0; c < MAXCAND; ++c) {
            int my = 0x7FFFFFFF;
#pragma unroll
            for (int e = 0; e < 8; ++e) {
                int g = (e < 4) ? tid * 4 + e : (tid + 256) * 4 + (e - 4);
                if (v[e] > thr && g > last) my = min(my, g);
            }
#pragma unroll
            for (int off = 16; off > 0; off >>= 1)
                my = min(my, __shfl_xor_sync(0xFFFFFFFFu, my, off));
            __syncthreads();
            if (lane == 0) swi[warp] = my;
            __syncthreads();
            int fnd = swi[0];
#pragma unroll
            for (int ww = 1; ww < 8; ++ww) fnd = min(fnd, swi[ww]);
            if (fnd == 0x7FFFFFFF) break;
            cand[ccount++] = fnd;
            last = fnd;
        }

        for (int d = tid; d < DD; d += 256) {
            sx[d] = x[(size_t)n * DD + d];
            for (int c = 0; c < ccount; ++c)
                scs[c][d] = cb[(size_t)cand[c] * DD + d];
        }
        __syncthreads();

        if (tid < ccount) {
            const float* cr = scs[tid];
            float s = 0.0f;
#pragma unroll 8
            for (int d = 0; d < DD; ++d) s = fmaf(sx[d], cr[d], s);
            s_exact[tid] = s;
        }
        __syncthreads();
        if (tid == 0) {
            float bvv = s_exact[0];
            int bii = cand[0];
            for (int c = 1; c < ccount; ++c)
                if (s_exact[c] > bvv) { bvv = s_exact[c]; bii = cand[c]; }
            s_final = bii;
        }
        __syncthreads();

        const int lbl = s_final;
        if (tid == 0) {
            if (labels_are_i64) ((long long*)labels)[n] = (long long)lbl;
            else                ((float*)labels)[n] = (float)lbl;
        }
        if (tid < 128) {
            float4 c = ((const float4*)(cb + (size_t)lbl * DD))[tid];
            ((float4*)(preds + (size_t)n * DD))[tid] = c;
        }
        __syncthreads();
    }
}

// ---------------------------------------------------------------------------
// Launch
// ---------------------------------------------------------------------------
extern "C" void kernel_launch(void* const* d_in, const int* in_sizes, int n_in,
                              void* d_out, int out_size)
{
    const float* x  = (const float*)d_in[0];   // [N, D]
    const float* cb = (const float*)d_in[1];   // [K, D]

    float* out = (float*)d_out;
    const size_t predsSz = (size_t)NN * DD;
    const size_t simsSz  = (size_t)NN * KK;

    size_t labelElems;
    int labels_are_i64;
    if ((size_t)(unsigned)out_size == predsSz + 2 * (size_t)NN + simsSz) {
        labelElems = 2 * (size_t)NN; labels_are_i64 = 1;
    } else {
        labelElems = (size_t)NN;     labels_are_i64 = 0;
    }

    float* preds  = out;
    void*  labels = (void*)(out + predsSz);
    float* sims   = out + predsSz + labelElems;

    static int attr_set = 0;
    if (!attr_set) {
        cudaFuncSetAttribute(gemm_f16_kernel,
                             cudaFuncAttributeMaxDynamicSharedMemorySize, SMEM_BYTES);
        attr_set = 1;
    }

    // fp16 pre-conversion (also resets the worklist counter)
    half* xh_p;  cudaGetSymbolAddress((void**)&xh_p,  g_xh);
    half* cbh_p; cudaGetSymbolAddress((void**)&cbh_p, g_cbh);
    cvt_f16_kernel<<<(NN * DD / 4) / 256, 256>>>((const float4*)x,  (uint2*)xh_p);
    cvt_f16_kernel<<<(KK * DD / 4) / 256, 256>>>((const float4*)cb, (uint2*)cbh_p);

    dim3 grid(KK / BN, NN / BM);   // (16, 1024)
    gemm_f16_kernel<<<grid, 256, SMEM_BYTES>>>(sims);
    reduce_label_kernel<<<NN / 8, 256>>>(cb, preds, labels, labels_are_i64);
    fixup_kernel<<<2048, 256>>>(sims, cb, x, preds, labels, labels_are_i64);
}